// round 1
// baseline (speedup 1.0000x reference)
#include <cuda_runtime.h>
#include <math.h>

#define B_TOTAL 8192
#define INDIM   784
#define NN      30
#define ND      20
#define NOUT    10
#define DK      16

#define R1      256   // batch rows per k1 block
#define KC      16    // k-chunk for k1
#define RB      8     // batch rows per k2 block
#define T2      640   // k2 threads

// scratch: u = squash(relu(relu(x@W1+b1)@W2+b2))  [B, 30, 20]
__device__ float g_u[(size_t)B_TOTAL * NN * ND];

// ---------------------------------------------------------------------------
// K1: grouped GEMM1 (+bias+relu) fused with GEMM2 (+bias+relu) and squash.
// grid = (B/256, 30), block = 128 threads.
// Thread tile: 8 rows x 5 cols of the [256 x 20] output tile.
// ---------------------------------------------------------------------------
__global__ __launch_bounds__(128) void k1_gemm(
    const float* __restrict__ x,   // [B, 784]
    const float* __restrict__ W1,  // [30, 784, 20]
    const float* __restrict__ b1,  // [30, 20]
    const float* __restrict__ W2,  // [30, 20, 20]
    const float* __restrict__ b2)  // [30, 20]
{
    __shared__ __align__(16) float xs[KC][R1];     // x chunk, transposed [k][row]
    __shared__ float ws[KC][ND];                   // W1 chunk
    __shared__ float hs[R1][ND + 1];               // h1 tile (padded)
    __shared__ float ws2[ND][ND];
    __shared__ float b2s[ND];

    const int net  = blockIdx.y;
    const int row0 = blockIdx.x * R1;
    const int tid  = threadIdx.x;
    const int cg   = tid & 3;     // col group: 5 cols each
    const int rg   = tid >> 2;    // row group: 8 rows each

    float acc[8][5];
    #pragma unroll
    for (int i = 0; i < 8; i++)
        #pragma unroll
        for (int j = 0; j < 5; j++) acc[i][j] = 0.f;

    const float* w1n = W1 + (size_t)net * INDIM * ND;

    for (int kc0 = 0; kc0 < INDIM; kc0 += KC) {
        // load x chunk [256 x 16] transposed into xs[k][row]
        #pragma unroll
        for (int l = 0; l < 8; l++) {
            int it = tid + l * 128;          // 0..1023
            int r  = it >> 2;
            int k4 = it & 3;
            float4 v = *(const float4*)(x + (size_t)(row0 + r) * INDIM + kc0 + k4 * 4);
            xs[k4 * 4 + 0][r] = v.x;
            xs[k4 * 4 + 1][r] = v.y;
            xs[k4 * 4 + 2][r] = v.z;
            xs[k4 * 4 + 3][r] = v.w;
        }
        // load W1 chunk [16 x 20]
        for (int it = tid; it < KC * ND; it += 128) {
            int kk = it / ND, c = it % ND;
            ws[kk][c] = w1n[(size_t)(kc0 + kk) * ND + c];
        }
        __syncthreads();

        #pragma unroll
        for (int kk = 0; kk < KC; kk++) {
            float4 xa = *(const float4*)&xs[kk][rg * 8];
            float4 xb = *(const float4*)&xs[kk][rg * 8 + 4];
            float xv[8] = {xa.x, xa.y, xa.z, xa.w, xb.x, xb.y, xb.z, xb.w};
            float wv[5];
            #pragma unroll
            for (int j = 0; j < 5; j++) wv[j] = ws[kk][cg * 5 + j];
            #pragma unroll
            for (int i = 0; i < 8; i++)
                #pragma unroll
                for (int j = 0; j < 5; j++)
                    acc[i][j] += xv[i] * wv[j];
        }
        __syncthreads();
    }

    // bias + relu -> hs
    #pragma unroll
    for (int j = 0; j < 5; j++) {
        float bb = b1[net * ND + cg * 5 + j];
        #pragma unroll
        for (int i = 0; i < 8; i++) {
            float v = acc[i][j] + bb;
            hs[rg * 8 + i][cg * 5 + j] = v > 0.f ? v : 0.f;
        }
    }
    for (int it = tid; it < ND * ND; it += 128)
        ws2[it / ND][it % ND] = W2[net * ND * ND + it];
    if (tid < ND) b2s[tid] = b2[net * ND + tid];
    __syncthreads();

    // GEMM2 + relu + squash: 2 rows per thread
    #pragma unroll
    for (int rr = 0; rr < 2; rr++) {
        int r = tid * 2 + rr;
        float h[ND];
        #pragma unroll
        for (int d = 0; d < ND; d++) h[d] = hs[r][d];
        float h2[ND];
        float sq = 0.f;
        #pragma unroll
        for (int e = 0; e < ND; e++) {
            float s = b2s[e];
            #pragma unroll
            for (int d = 0; d < ND; d++) s += h[d] * ws2[d][e];
            s = s > 0.f ? s : 0.f;
            h2[e] = s;
            sq += s * s;
        }
        float scale = (sq / (1.f + sq)) / sqrtf(sq);
        float* up = g_u + (size_t)(row0 + r) * (NN * ND) + net * ND;
        #pragma unroll
        for (int e = 0; e < ND; e++) up[e] = scale * h2[e];
    }
}

// ---------------------------------------------------------------------------
// K2: priors (u @ route) + dynamic routing, fully fused; priors live in smem.
// grid = B/8, block = 640 threads, dynamic smem ~197 KB.
// ---------------------------------------------------------------------------
__global__ __launch_bounds__(T2, 1) void k2_route(
    const float* __restrict__ route,  // [10, 30, 20, 16]
    float* __restrict__ out)          // [B, 10, 16]
{
    extern __shared__ __align__(16) float sm[];
    float* u_s  = sm;           // [30][20][8]           4800
    float* p_s  = sm + 4800;    // [8][10][30][16]      38400
    float* l_s  = sm + 43200;   // [8][10][30] logits    2400
    float* pr_s = sm + 45600;   // [8][10][30] probs     2400
    float* v_s  = sm + 48000;   // [8][10][16]           1280
    float* sc_s = sm + 49280;   // [8][10]                 80

    const int tid = threadIdx.x;
    const int r0  = blockIdx.x * RB;

    // load u for 8 rows, transposed to [c][r] (c = n*20+d)
    for (int it = tid; it < RB * NN * ND; it += T2) {
        int r = it / (NN * ND);
        int c = it % (NN * ND);
        u_s[c * RB + r] = g_u[(size_t)(r0 + r) * (NN * ND) + c];
    }
    __syncthreads();

    // ---- priors: thread = (o, n, kg); 8 rows x 8 k accumulators ----
    if (tid < 600) {
        int o   = tid / 60;
        int rem = tid % 60;
        int n   = rem >> 1;
        int kg  = rem & 1;
        float acc[RB][8];
        #pragma unroll
        for (int i = 0; i < RB; i++)
            #pragma unroll
            for (int j = 0; j < 8; j++) acc[i][j] = 0.f;

        const float* rp = route + (size_t)((o * NN + n) * ND) * DK + kg * 8;
        const float* up = u_s + (n * ND) * RB;
        #pragma unroll 4
        for (int d = 0; d < ND; d++) {
            float4 ua = *(const float4*)(up + d * RB);
            float4 ub = *(const float4*)(up + d * RB + 4);
            float4 ra = *(const float4*)(rp + (size_t)d * DK);
            float4 rb = *(const float4*)(rp + (size_t)d * DK + 4);
            float uv[8] = {ua.x, ua.y, ua.z, ua.w, ub.x, ub.y, ub.z, ub.w};
            float wv[8] = {ra.x, ra.y, ra.z, ra.w, rb.x, rb.y, rb.z, rb.w};
            #pragma unroll
            for (int i = 0; i < RB; i++)
                #pragma unroll
                for (int j = 0; j < 8; j++)
                    acc[i][j] += uv[i] * wv[j];
        }
        #pragma unroll
        for (int i = 0; i < RB; i++) {
            float* pp = p_s + ((i * NOUT + o) * NN + n) * DK + kg * 8;
            *(float4*)pp       = make_float4(acc[i][0], acc[i][1], acc[i][2], acc[i][3]);
            *(float4*)(pp + 4) = make_float4(acc[i][4], acc[i][5], acc[i][6], acc[i][7]);
        }
    }
    __syncthreads();

    // ---- dynamic routing, 3 iterations ----
    for (int iter = 0; iter < 3; iter++) {
        if (iter > 0) {
            // softmax over o, per (r, n)
            if (tid < RB * NN) {
                int r = tid / NN, n = tid % NN;
                float l[NOUT];
                float mx = -1e30f;
                #pragma unroll
                for (int o = 0; o < NOUT; o++) {
                    l[o] = l_s[(r * NOUT + o) * NN + n];
                    mx = fmaxf(mx, l[o]);
                }
                float ssum = 0.f;
                #pragma unroll
                for (int o = 0; o < NOUT; o++) { l[o] = expf(l[o] - mx); ssum += l[o]; }
                float inv = 1.f / ssum;
                #pragma unroll
                for (int o = 0; o < NOUT; o++)
                    pr_s[(r * NOUT + o) * NN + n] = l[o] * inv;
            }
            __syncthreads();
        }

        // s[r,o,k] = sum_n probs * priors  -> v_s (pre-squash)
        for (int it = tid; it < RB * NOUT * DK; it += T2) {
            int r  = it / (NOUT * DK);
            int ok = it % (NOUT * DK);
            int o  = ok / DK, k = ok % DK;
            const float* pp = p_s + ((r * NOUT + o) * NN) * DK + k;
            float s = 0.f;
            if (iter == 0) {
                #pragma unroll
                for (int n = 0; n < NN; n++) s += pp[n * DK];
                s *= 0.1f;
            } else {
                const float* prp = pr_s + (r * NOUT + o) * NN;
                #pragma unroll
                for (int n = 0; n < NN; n++) s += prp[n] * pp[n * DK];
            }
            v_s[it] = s;
        }
        __syncthreads();

        // squash scale per (r, o)
        if (tid < RB * NOUT) {
            const float* vp = v_s + tid * DK;
            float sq = 0.f;
            #pragma unroll
            for (int k = 0; k < DK; k++) sq += vp[k] * vp[k];
            sc_s[tid] = (sq / (1.f + sq)) / sqrtf(sq);
        }
        __syncthreads();

        for (int it = tid; it < RB * NOUT * DK; it += T2)
            v_s[it] *= sc_s[it / DK];
        __syncthreads();

        if (iter < 2) {
            // logits[r,o,n] += sum_k priors * v
            for (int it = tid; it < RB * NOUT * NN; it += T2) {
                int r  = it / (NOUT * NN);
                int on = it % (NOUT * NN);
                int o  = on / NN, n = on % NN;
                const float* pp = p_s + ((r * NOUT + o) * NN + n) * DK;
                const float* vp = v_s + (r * NOUT + o) * DK;
                float s = 0.f;
                #pragma unroll
                for (int k = 0; k < DK; k++) s += pp[k] * vp[k];
                l_s[it] = (iter == 0) ? s : (l_s[it] + s);
            }
            __syncthreads();
        }
    }

    // write output [B,10,16]
    for (int it = tid; it < RB * NOUT * DK; it += T2) {
        int r = it / (NOUT * DK);
        out[(size_t)(r0 + r) * (NOUT * DK) + (it % (NOUT * DK))] = v_s[it];
    }
}

// ---------------------------------------------------------------------------
extern "C" void kernel_launch(void* const* d_in, const int* in_sizes, int n_in,
                              void* d_out, int out_size)
{
    const float* x     = (const float*)d_in[0];
    const float* W1    = (const float*)d_in[1];
    const float* b1    = (const float*)d_in[2];
    const float* W2    = (const float*)d_in[3];
    const float* b2    = (const float*)d_in[4];
    const float* route = (const float*)d_in[5];
    float* out = (float*)d_out;

    dim3 g1(B_TOTAL / R1, NN);
    k1_gemm<<<g1, 128>>>(x, W1, b1, W2, b2);

    const int smem = 49360 * (int)sizeof(float);  // 197440 B
    cudaFuncSetAttribute(k2_route, cudaFuncAttributeMaxDynamicSharedMemorySize, smem);
    k2_route<<<B_TOTAL / RB, T2, smem>>>(route, out);
}

// round 2
// speedup vs baseline: 1.4295x; 1.4295x over previous
#include <cuda_runtime.h>
#include <math.h>

typedef unsigned long long u64;

#define B_TOTAL 8192
#define INDIM   784
#define NN      30
#define ND      20
#define NOUT    10
#define DK      16

// ---- k1 tiling ----
#define R1    256
#define KC    16
#define NCH   (INDIM / KC)   // 49
#define XPAD  260            // x-tile row stride (breaks STS conflicts, keeps 16B align)

// ---- k2 tiling ----
#define RB    8
#define T2    640
#define UPAD  12                 // u_s row stride (16B-align friendly, conflict-free-ish)
#define KST   34                 // p_s k-stride   (34 mod 32 = 2)
#define OST   (DK * KST + 2)     // 546 (mod 32 = 2)
#define RST   (NOUT * OST)       // 5460

// scratch: u = squash(relu(relu(x@W1+b1)@W2+b2))  [B, 30, 20]
__device__ float g_u[(size_t)B_TOTAL * NN * ND];

// ---------------------------------------------------------------------------
// packed f32x2 helpers (SASS FFMA2 path — only reachable via PTX)
// ---------------------------------------------------------------------------
__device__ __forceinline__ u64 pack2(float lo, float hi) {
    u64 r; asm("mov.b64 %0, {%1,%2};" : "=l"(r) : "f"(lo), "f"(hi)); return r;
}
__device__ __forceinline__ void unpack2(u64 v, float& lo, float& hi) {
    asm("mov.b64 {%0,%1}, %2;" : "=f"(lo), "=f"(hi) : "l"(v));
}
__device__ __forceinline__ void fma2(u64& d, u64 a, u64 b) {
    asm("fma.rn.f32x2 %0, %1, %2, %0;" : "+l"(d) : "l"(a), "l"(b));
}

// ---------------------------------------------------------------------------
// K1: GEMM1 (packed f32x2, double-buffered) + GEMM2 + squash -> g_u
// grid = (32, 30), block = 128. Thread tile: 8 rows (4 packed pairs) x 5 cols.
// ---------------------------------------------------------------------------
__global__ __launch_bounds__(128) void k1_gemm(
    const float* __restrict__ x,   // [B, 784]
    const float* __restrict__ W1,  // [30, 784, 20]
    const float* __restrict__ b1,  // [30, 20]
    const float* __restrict__ W2,  // [30, 20, 20]
    const float* __restrict__ b2)  // [30, 20]
{
    extern __shared__ __align__(16) float sm1[];
    float*  xs  = sm1;                                   // [2][KC][XPAD]  8320 f
    float2* wsd = (float2*)(sm1 + 2 * KC * XPAD);        // [2][KC][ND]    1280 f
    float*  hs  = sm1 + 2 * KC * XPAD + 2 * KC * ND * 2; // [R1][21]       5376 f
    float*  ws2 = hs + R1 * 21;                          // [20][20]        400 f
    float*  b2s = ws2 + ND * ND;                         //                  20 f

    const int net  = blockIdx.y;
    const int row0 = blockIdx.x * R1;
    const int tid  = threadIdx.x;
    const int cg   = tid & 3;     // 5 cols each
    const int rg   = tid >> 2;    // 8 rows each
    const float* w1n = W1 + (size_t)net * INDIM * ND;

    u64 acc[4][5];
    #pragma unroll
    for (int i = 0; i < 4; i++)
        #pragma unroll
        for (int j = 0; j < 5; j++) acc[i][j] = 0ull;   // (0.f, 0.f)

    float4 xr[8];
    float  wr0, wr1, wr2 = 0.f;

    // chunk global loads -> regs
    #define LDG_CHUNK(kc0)                                                        \
        do {                                                                      \
            _Pragma("unroll")                                                     \
            for (int l = 0; l < 8; l++)                                           \
                xr[l] = *(const float4*)(x + (size_t)(row0 + rg + l * 32) * INDIM \
                                           + (kc0) + cg * 4);                     \
            wr0 = w1n[(size_t)(kc0) * ND + tid];                                  \
            wr1 = w1n[(size_t)(kc0) * ND + tid + 128];                            \
            if (tid < 64) wr2 = w1n[(size_t)(kc0) * ND + tid + 256];              \
        } while (0)

    // regs -> smem buffer
    #define STS_CHUNK(buf)                                                        \
        do {                                                                      \
            float* xb = xs + (buf) * KC * XPAD;                                   \
            _Pragma("unroll")                                                     \
            for (int l = 0; l < 8; l++) {                                         \
                xb[(cg * 4 + 0) * XPAD + rg + l * 32] = xr[l].x;                  \
                xb[(cg * 4 + 1) * XPAD + rg + l * 32] = xr[l].y;                  \
                xb[(cg * 4 + 2) * XPAD + rg + l * 32] = xr[l].z;                  \
                xb[(cg * 4 + 3) * XPAD + rg + l * 32] = xr[l].w;                  \
            }                                                                     \
            float2* wb = wsd + (buf) * KC * ND;                                   \
            wb[tid]       = make_float2(wr0, wr0);                                \
            wb[tid + 128] = make_float2(wr1, wr1);                                \
            if (tid < 64) wb[tid + 256] = make_float2(wr2, wr2);                  \
        } while (0)

    LDG_CHUNK(0);
    STS_CHUNK(0);
    __syncthreads();

    for (int c = 0; c < NCH; c++) {
        const int cur = c & 1;
        if (c + 1 < NCH) LDG_CHUNK((c + 1) * KC);

        const float*  xb = xs  + cur * KC * XPAD;
        const float2* wb = wsd + cur * KC * ND;
        #pragma unroll
        for (int kk = 0; kk < KC; kk++) {
            ulonglong2 xa = *(const ulonglong2*)(xb + kk * XPAD + rg * 8);
            ulonglong2 xc = *(const ulonglong2*)(xb + kk * XPAD + rg * 8 + 4);
            u64 xv[4] = {xa.x, xa.y, xc.x, xc.y};
            u64 wv[5];
            #pragma unroll
            for (int j = 0; j < 5; j++)
                wv[j] = *(const u64*)(wb + kk * ND + cg * 5 + j);
            #pragma unroll
            for (int i = 0; i < 4; i++)
                #pragma unroll
                for (int j = 0; j < 5; j++)
                    fma2(acc[i][j], xv[i], wv[j]);
        }

        if (c + 1 < NCH) STS_CHUNK((c + 1) & 1);
        __syncthreads();
    }

    // bias + relu -> hs
    #pragma unroll
    for (int j = 0; j < 5; j++) {
        float bb = b1[net * ND + cg * 5 + j];
        #pragma unroll
        for (int i = 0; i < 4; i++) {
            float lo, hi; unpack2(acc[i][j], lo, hi);
            float v0 = lo + bb, v1 = hi + bb;
            hs[(rg * 8 + 2 * i    ) * 21 + cg * 5 + j] = v0 > 0.f ? v0 : 0.f;
            hs[(rg * 8 + 2 * i + 1) * 21 + cg * 5 + j] = v1 > 0.f ? v1 : 0.f;
        }
    }
    for (int it = tid; it < ND * ND; it += 128) ws2[it] = W2[net * ND * ND + it];
    if (tid < ND) b2s[tid] = b2[net * ND + tid];
    __syncthreads();

    // GEMM2 + relu + squash: 2 rows per thread
    #pragma unroll
    for (int rr = 0; rr < 2; rr++) {
        int r = tid * 2 + rr;
        float h[ND];
        #pragma unroll
        for (int d = 0; d < ND; d++) h[d] = hs[r * 21 + d];
        float h2[ND];
        float sq = 0.f;
        #pragma unroll
        for (int e = 0; e < ND; e++) {
            float s = b2s[e];
            #pragma unroll
            for (int d = 0; d < ND; d++) s += h[d] * ws2[d * ND + e];
            s = s > 0.f ? s : 0.f;
            h2[e] = s;
            sq += s * s;
        }
        float scale = (sq / (1.f + sq)) / sqrtf(sq);
        float* up = g_u + (size_t)(row0 + r) * (NN * ND) + net * ND;
        #pragma unroll
        for (int e = 0; e < ND; e++) up[e] = scale * h2[e];
    }
}

// ---------------------------------------------------------------------------
// K2: priors (packed f32x2, conflict-free mapping) + dynamic routing in smem.
// grid = B/8, block = 640, dyn smem ~223 KB.
// ---------------------------------------------------------------------------
__global__ __launch_bounds__(T2, 1) void k2_route(
    const float* __restrict__ route,  // [10, 30, 20, 16]
    float* __restrict__ out)          // [B, 10, 16]
{
    extern __shared__ __align__(16) float sm[];
    float* u_s  = sm;                       // [600][UPAD]            7200
    float* p_s  = sm + 7200;                // [8][RST]              43680
    float* l_s  = p_s + RB * RST;           // [8][10][30]            2400
    float* pr_s = l_s + RB * NOUT * NN;     // [8][10][30]            2400
    float* v_s  = pr_s + RB * NOUT * NN;    // [8][10][16]            1280
    float* sc_s = v_s + RB * NOUT * DK;     // [8][10]                  80

    const int tid = threadIdx.x;
    const int r0  = blockIdx.x * RB;

    // load u for 8 rows, transposed [c][row] with padded stride
    for (int it = tid; it < RB * NN * ND; it += T2) {
        int r = it / (NN * ND);
        int c = it % (NN * ND);
        u_s[c * UPAD + r] = g_u[(size_t)(r0 + r) * (NN * ND) + c];
    }
    __syncthreads();

    // ---- priors: thread = (n, o, kg); u loads broadcast within warp ----
    if (tid < 600) {
        const int n  = tid / 20;
        const int oo = tid % 20;
        const int o  = oo >> 1;
        const int kg = oo & 1;

        u64 acc[4][8];
        #pragma unroll
        for (int i = 0; i < 4; i++)
            #pragma unroll
            for (int j = 0; j < 8; j++) acc[i][j] = 0ull;

        const float* rp = route + (size_t)((o * NN + n) * ND) * DK + kg * 8;
        const float* up = u_s + (n * ND) * UPAD;

        #pragma unroll 4
        for (int d = 0; d < ND; d++) {
            ulonglong2 ua = *(const ulonglong2*)(up + d * UPAD);      // rows 0..3
            ulonglong2 ub = *(const ulonglong2*)(up + d * UPAD + 4);  // rows 4..7
            u64 uv[4] = {ua.x, ua.y, ub.x, ub.y};
            float4 ra = *(const float4*)(rp + (size_t)d * DK);
            float4 rb = *(const float4*)(rp + (size_t)d * DK + 4);
            u64 wv[8] = {pack2(ra.x, ra.x), pack2(ra.y, ra.y),
                         pack2(ra.z, ra.z), pack2(ra.w, ra.w),
                         pack2(rb.x, rb.x), pack2(rb.y, rb.y),
                         pack2(rb.z, rb.z), pack2(rb.w, rb.w)};
            #pragma unroll
            for (int i = 0; i < 4; i++)
                #pragma unroll
                for (int j = 0; j < 8; j++)
                    fma2(acc[i][j], uv[i], wv[j]);
        }

        #pragma unroll
        for (int i = 0; i < 4; i++)
            #pragma unroll
            for (int j = 0; j < 8; j++) {
                float lo, hi; unpack2(acc[i][j], lo, hi);
                p_s[(2 * i    ) * RST + o * OST + (kg * 8 + j) * KST + n] = lo;
                p_s[(2 * i + 1) * RST + o * OST + (kg * 8 + j) * KST + n] = hi;
            }
    }
    __syncthreads();

    // ---- dynamic routing, 3 iterations ----
    for (int iter = 0; iter < 3; iter++) {
        if (iter > 0) {
            // softmax over o, per (r, n)
            if (tid < RB * NN) {
                int r = tid / NN, n = tid % NN;
                float l[NOUT];
                float mx = -1e30f;
                #pragma unroll
                for (int o = 0; o < NOUT; o++) {
                    l[o] = l_s[(r * NOUT + o) * NN + n];
                    mx = fmaxf(mx, l[o]);
                }
                float ssum = 0.f;
                #pragma unroll
                for (int o = 0; o < NOUT; o++) { l[o] = expf(l[o] - mx); ssum += l[o]; }
                float inv = 1.f / ssum;
                #pragma unroll
                for (int o = 0; o < NOUT; o++)
                    pr_s[(r * NOUT + o) * NN + n] = l[o] * inv;
            }
            __syncthreads();
        }

        // s[r,o,k] = sum_n probs * priors
        for (int it = tid; it < RB * NOUT * DK; it += T2) {
            int r  = it / (NOUT * DK);
            int ok = it % (NOUT * DK);
            int o  = ok / DK, k = ok % DK;
            const float* pp = p_s + r * RST + o * OST + k * KST;
            float s = 0.f;
            if (iter == 0) {
                #pragma unroll
                for (int n = 0; n < NN; n++) s += pp[n];
                s *= 0.1f;
            } else {
                const float* prp = pr_s + (r * NOUT + o) * NN;
                #pragma unroll
                for (int n = 0; n < NN; n++) s += prp[n] * pp[n];
            }
            v_s[it] = s;
        }
        __syncthreads();

        // squash scale per (r, o)
        if (tid < RB * NOUT) {
            const float* vp = v_s + tid * DK;
            float sq = 0.f;
            #pragma unroll
            for (int k = 0; k < DK; k++) sq += vp[k] * vp[k];
            sc_s[tid] = (sq / (1.f + sq)) / sqrtf(sq);
        }
        __syncthreads();

        for (int it = tid; it < RB * NOUT * DK; it += T2)
            v_s[it] *= sc_s[it / DK];
        __syncthreads();

        if (iter < 2) {
            // logits[r,o,n] += sum_k priors * v
            for (int it = tid; it < RB * NOUT * NN; it += T2) {
                int r  = it / (NOUT * NN);
                int on = it % (NOUT * NN);
                int o  = on / NN, n = on % NN;
                const float* pp = p_s + r * RST + o * OST + n;
                const float* vp = v_s + (r * NOUT + o) * DK;
                float s = 0.f;
                #pragma unroll
                for (int k = 0; k < DK; k++) s += pp[k * KST] * vp[k];
                l_s[it] = (iter == 0) ? s : (l_s[it] + s);
            }
            __syncthreads();
        }
    }

    // write output [B,10,16]
    for (int it = tid; it < RB * NOUT * DK; it += T2) {
        int r = it / (NOUT * DK);
        out[(size_t)(r0 + r) * (NOUT * DK) + (it % (NOUT * DK))] = v_s[it];
    }
}

// ---------------------------------------------------------------------------
extern "C" void kernel_launch(void* const* d_in, const int* in_sizes, int n_in,
                              void* d_out, int out_size)
{
    const float* x     = (const float*)d_in[0];
    const float* W1    = (const float*)d_in[1];
    const float* b1    = (const float*)d_in[2];
    const float* W2    = (const float*)d_in[3];
    const float* b2    = (const float*)d_in[4];
    const float* route = (const float*)d_in[5];
    float* out = (float*)d_out;

    const int smem1 = (2 * KC * XPAD + 2 * KC * ND * 2 + R1 * 21 + ND * ND + ND)
                      * (int)sizeof(float);                       // 61584 B
    cudaFuncSetAttribute(k1_gemm, cudaFuncAttributeMaxDynamicSharedMemorySize, smem1);
    dim3 g1(B_TOTAL / R1, NN);
    k1_gemm<<<g1, 128, smem1>>>(x, W1, b1, W2, b2);

    const int smem2 = (7200 + RB * RST + 2 * RB * NOUT * NN + RB * NOUT * DK
                       + RB * NOUT) * (int)sizeof(float);         // 228160 B
    cudaFuncSetAttribute(k2_route, cudaFuncAttributeMaxDynamicSharedMemorySize, smem2);
    k2_route<<<B_TOTAL / RB, T2, smem2>>>(route, out);
}

// round 4
// speedup vs baseline: 1.5865x; 1.1098x over previous
#include <cuda_runtime.h>
#include <cuda_bf16.h>
#include <math.h>
#include <stdint.h>

typedef unsigned long long u64;

#define B_TOTAL 8192
#define INDIM   784
#define NN      30
#define ND      20
#define NOUT    10
#define DK      16

// ---- k1 HMMA tiling ----
#define GNETS   3                 // nets per group
#define NGRP    10                // groups
#define SLOT    24                // padded cols per net
#define NT      9                 // n8 tiles per group (3 nets x 3)
#define KS49    49                // 784 / 16
#define NBAND   (B_TOTAL / 16)    // 512 m16 bands
#define HSTR    76                // epilogue smem row stride

// ---- k2 tiling (unchanged) ----
#define RB    8
#define T2    640
#define UPAD  12
#define KST   34
#define OST   (DK * KST + 2)
#define RST   (NOUT * OST)

// ---- device scratch ----
__device__ float g_u[(size_t)B_TOTAL * NN * ND];
__device__ uint4 g_xhf[(size_t)NBAND * KS49 * 32];   // A frags hi  (12.8MB)
__device__ uint4 g_xlf[(size_t)NBAND * KS49 * 32];   // A frags lo
__device__ uint2 g_wbhf[(size_t)NGRP * KS49 * NT * 32];  // B frags hi (1.13MB)
__device__ uint2 g_wblf[(size_t)NGRP * KS49 * NT * 32];  // B frags lo

// ---------------------------------------------------------------------------
// helpers
// ---------------------------------------------------------------------------
__device__ __forceinline__ uint32_t pbf2(float a, float b) {
    __nv_bfloat162 t = __floats2bfloat162_rn(a, b);   // a -> low half
    return *(uint32_t*)&t;
}
__device__ __forceinline__ void split2(float v, float& h, float& l) {
    __nv_bfloat16 hb = __float2bfloat16(v);
    h = __bfloat162float(hb);
    l = v - h;
}
#define MMA_BF16(d, a, b) \
    asm volatile("mma.sync.aligned.m16n8k16.row.col.f32.bf16.bf16.f32 " \
        "{%0,%1,%2,%3}, {%4,%5,%6,%7}, {%8,%9}, {%0,%1,%2,%3};" \
        : "+f"((d)[0]), "+f"((d)[1]), "+f"((d)[2]), "+f"((d)[3]) \
        : "r"((a).x), "r"((a).y), "r"((a).z), "r"((a).w), \
          "r"((b).x), "r"((b).y))

// ---------------------------------------------------------------------------
// k0x: pack x into m16n8k16 A-fragment layout, split bf16 hi/lo
// one thread = one (band, kstep, lane) -> uint4 hi + uint4 lo
// ---------------------------------------------------------------------------
__global__ __launch_bounds__(256) void k0_pack_x(const float* __restrict__ x) {
    int gid = blockIdx.x * 256 + threadIdx.x;
    if (gid >= NBAND * KS49 * 32) return;
    int lane = gid & 31;
    int t    = gid >> 5;
    int ks   = t % KS49;
    int band = t / KS49;

    int r0 = band * 16 + (lane >> 2);
    int c0 = ks * 16 + (lane & 3) * 2;
    const float* p0 = x + (size_t)r0 * INDIM + c0;
    const float* p1 = p0 + 8 * INDIM;

    float v[8] = { p0[0], p0[1], p1[0], p1[1], p0[8], p0[9], p1[8], p1[9] };
    float h[8], l[8];
    #pragma unroll
    for (int i = 0; i < 8; i++) split2(v[i], h[i], l[i]);

    g_xhf[gid] = make_uint4(pbf2(h[0], h[1]), pbf2(h[2], h[3]),
                            pbf2(h[4], h[5]), pbf2(h[6], h[7]));
    g_xlf[gid] = make_uint4(pbf2(l[0], l[1]), pbf2(l[2], l[3]),
                            pbf2(l[4], l[5]), pbf2(l[6], l[7]));
}

// ---------------------------------------------------------------------------
// k0w: pack W1 into m16n8k16 B-fragment layout (col-major n8k16), hi/lo
// one thread = one (grp, kstep, tile, lane) -> uint2 hi + uint2 lo
// ---------------------------------------------------------------------------
__global__ __launch_bounds__(256) void k0_pack_w(const float* __restrict__ W1) {
    int gid = blockIdx.x * 256 + threadIdx.x;
    if (gid >= NGRP * KS49 * NT * 32) return;
    int lane = gid & 31;
    int t    = (gid >> 5) % NT;
    int ks   = ((gid >> 5) / NT) % KS49;
    int grp  = (gid >> 5) / (NT * KS49);

    int net = grp * GNETS + t / 3;
    int col = (t % 3) * 8 + (lane >> 2);
    int k0  = ks * 16 + (lane & 3) * 2;

    float v[4] = {0.f, 0.f, 0.f, 0.f};
    if (col < ND) {
        const float* wp = W1 + ((size_t)net * INDIM + k0) * ND + col;
        v[0] = wp[0];           // k0
        v[1] = wp[ND];          // k0+1
        v[2] = wp[8 * ND];      // k0+8
        v[3] = wp[9 * ND];      // k0+9
    }
    float h[4], l[4];
    #pragma unroll
    for (int i = 0; i < 4; i++) split2(v[i], h[i], l[i]);

    g_wbhf[gid] = make_uint2(pbf2(h[0], h[1]), pbf2(h[2], h[3]));
    g_wblf[gid] = make_uint2(pbf2(l[0], l[1]), pbf2(l[2], l[3]));
}

// ---------------------------------------------------------------------------
// k1: HMMA split-bf16 GEMM1 + fused GEMM2/squash epilogue
// grid = (64, 10), block = 256 (8 warps x m16). N = 72 (3 nets x 24 slots).
// ---------------------------------------------------------------------------
__global__ __launch_bounds__(256) void k1_mma(
    const float* __restrict__ b1,   // [30, 20]
    const float* __restrict__ W2,   // [30, 20, 20]
    const float* __restrict__ b2)   // [30, 20]
{
    extern __shared__ __align__(16) float sm[];
    float* hs  = sm;                        // [128][HSTR]
    float* ws2 = sm + 128 * HSTR;           // [3][400]
    float* b1s = ws2 + GNETS * 400;         // [3][20]
    float* b2s = b1s + GNETS * ND;          // [3][20]

    const int tid  = threadIdx.x;
    const int w    = tid >> 5;
    const int lane = tid & 31;
    const int grp  = blockIdx.y;
    const int row0 = blockIdx.x * 128;

    // stage epilogue weights
    for (int it = tid; it < GNETS * 400; it += 256)
        ws2[it] = W2[(size_t)(grp * GNETS) * 400 + it];
    if (tid < GNETS * ND) {
        b1s[tid] = b1[grp * GNETS * ND + tid];
        b2s[tid] = b2[grp * GNETS * ND + tid];
    }

    float acc[NT][4];
    #pragma unroll
    for (int t = 0; t < NT; t++)
        #pragma unroll
        for (int i = 0; i < 4; i++) acc[t][i] = 0.f;

    const int band = blockIdx.x * 8 + w;
    const uint4* pah = g_xhf + (size_t)band * KS49 * 32 + lane;
    const uint4* pal = g_xlf + (size_t)band * KS49 * 32 + lane;
    const uint2* pbh = g_wbhf + (size_t)grp * KS49 * NT * 32 + lane;
    const uint2* pbl = g_wblf + (size_t)grp * KS49 * NT * 32 + lane;

    for (int ks = 0; ks < KS49; ks++) {
        uint4 ah = pah[ks * 32];
        uint4 al = pal[ks * 32];
        const uint2* bh = pbh + ks * NT * 32;
        const uint2* bl = pbl + ks * NT * 32;
        #pragma unroll
        for (int t = 0; t < NT; t++) {
            uint2 vh = bh[t * 32];
            uint2 vl = bl[t * 32];
            MMA_BF16(acc[t], ah, vh);   // xh * wh
            MMA_BF16(acc[t], al, vh);   // xl * wh
            MMA_BF16(acc[t], ah, vl);   // xh * wl
        }
    }

    // accumulators -> smem
    {
        const int rlo = w * 16 + (lane >> 2);
        const int cb  = (lane & 3) * 2;
        #pragma unroll
        for (int t = 0; t < NT; t++) {
            int col = t * 8 + cb;
            hs[rlo * HSTR + col]           = acc[t][0];
            hs[rlo * HSTR + col + 1]       = acc[t][1];
            hs[(rlo + 8) * HSTR + col]     = acc[t][2];
            hs[(rlo + 8) * HSTR + col + 1] = acc[t][3];
        }
    }
    __syncthreads();

    // epilogue: bias+relu, GEMM2+relu, squash -> g_u (exact fp32)
    for (int task = tid; task < 128 * GNETS; task += 256) {
        const int row = task / GNETS;
        const int g   = task % GNETS;
        const int net = grp * GNETS + g;
        float h[ND];
        #pragma unroll
        for (int c = 0; c < ND; c++) {
            float v = hs[row * HSTR + g * SLOT + c] + b1s[g * ND + c];
            h[c] = v > 0.f ? v : 0.f;
        }
        float h2[ND];
        float sq = 0.f;
        #pragma unroll
        for (int e = 0; e < ND; e++) {
            float s = b2s[g * ND + e];
            #pragma unroll
            for (int d = 0; d < ND; d++) s += h[d] * ws2[g * 400 + d * ND + e];
            s = s > 0.f ? s : 0.f;
            h2[e] = s;
            sq += s * s;
        }
        float scale = (sq / (1.f + sq)) / sqrtf(sq);
        float* up = g_u + (size_t)(row0 + row) * (NN * ND) + net * ND;
        #pragma unroll
        for (int e4 = 0; e4 < 5; e4++)
            *(float4*)(up + e4 * 4) = make_float4(scale * h2[e4*4],   scale * h2[e4*4+1],
                                                  scale * h2[e4*4+2], scale * h2[e4*4+3]);
    }
}

// ---------------------------------------------------------------------------
// K2: priors (packed f32x2) + dynamic routing (unchanged best version)
// ---------------------------------------------------------------------------
__device__ __forceinline__ u64 pack2(float lo, float hi) {
    u64 r; asm("mov.b64 %0, {%1,%2};" : "=l"(r) : "f"(lo), "f"(hi)); return r;
}
__device__ __forceinline__ void unpack2(u64 v, float& lo, float& hi) {
    asm("mov.b64 {%0,%1}, %2;" : "=f"(lo), "=f"(hi) : "l"(v));
}
__device__ __forceinline__ void fma2(u64& d, u64 a, u64 b) {
    asm("fma.rn.f32x2 %0, %1, %2, %0;" : "+l"(d) : "l"(a), "l"(b));
}

__global__ __launch_bounds__(T2, 1) void k2_route(
    const float* __restrict__ route,  // [10, 30, 20, 16]
    float* __restrict__ out)          // [B, 10, 16]
{
    extern __shared__ __align__(16) float sm[];
    float* u_s  = sm;                       // [600][UPAD]
    float* p_s  = sm + 7200;                // [8][RST]
    float* l_s  = p_s + RB * RST;
    float* pr_s = l_s + RB * NOUT * NN;
    float* v_s  = pr_s + RB * NOUT * NN;
    float* sc_s = v_s + RB * NOUT * DK;

    const int tid = threadIdx.x;
    const int r0  = blockIdx.x * RB;

    for (int it = tid; it < RB * NN * ND; it += T2) {
        int r = it / (NN * ND);
        int c = it % (NN * ND);
        u_s[c * UPAD + r] = g_u[(size_t)(r0 + r) * (NN * ND) + c];
    }
    __syncthreads();

    if (tid < 600) {
        const int n  = tid / 20;
        const int oo = tid % 20;
        const int o  = oo >> 1;
        const int kg = oo & 1;

        u64 acc[4][8];
        #pragma unroll
        for (int i = 0; i < 4; i++)
            #pragma unroll
            for (int j = 0; j < 8; j++) acc[i][j] = 0ull;

        const float* rp = route + (size_t)((o * NN + n) * ND) * DK + kg * 8;
        const float* up = u_s + (n * ND) * UPAD;

        #pragma unroll 4
        for (int d = 0; d < ND; d++) {
            ulonglong2 ua = *(const ulonglong2*)(up + d * UPAD);
            ulonglong2 ub = *(const ulonglong2*)(up + d * UPAD + 4);
            u64 uv[4] = {ua.x, ua.y, ub.x, ub.y};
            float4 ra = *(const float4*)(rp + (size_t)d * DK);
            float4 rb = *(const float4*)(rp + (size_t)d * DK + 4);
            u64 wv[8] = {pack2(ra.x, ra.x), pack2(ra.y, ra.y),
                         pack2(ra.z, ra.z), pack2(ra.w, ra.w),
                         pack2(rb.x, rb.x), pack2(rb.y, rb.y),
                         pack2(rb.z, rb.z), pack2(rb.w, rb.w)};
            #pragma unroll
            for (int i = 0; i < 4; i++)
                #pragma unroll
                for (int j = 0; j < 8; j++)
                    fma2(acc[i][j], uv[i], wv[j]);
        }

        #pragma unroll
        for (int i = 0; i < 4; i++)
            #pragma unroll
            for (int j = 0; j < 8; j++) {
                float lo, hi; unpack2(acc[i][j], lo, hi);
                p_s[(2 * i    ) * RST + o * OST + (kg * 8 + j) * KST + n] = lo;
                p_s[(2 * i + 1) * RST + o * OST + (kg * 8 + j) * KST + n] = hi;
            }
    }
    __syncthreads();

    for (int iter = 0; iter < 3; iter++) {
        if (iter > 0) {
            if (tid < RB * NN) {
                int r = tid / NN, n = tid % NN;
                float l[NOUT];
                float mx = -1e30f;
                #pragma unroll
                for (int o = 0; o < NOUT; o++) {
                    l[o] = l_s[(r * NOUT + o) * NN + n];
                    mx = fmaxf(mx, l[o]);
                }
                float ssum = 0.f;
                #pragma unroll
                for (int o = 0; o < NOUT; o++) { l[o] = expf(l[o] - mx); ssum += l[o]; }
                float inv = 1.f / ssum;
                #pragma unroll
                for (int o = 0; o < NOUT; o++)
                    pr_s[(r * NOUT + o) * NN + n] = l[o] * inv;
            }
            __syncthreads();
        }

        for (int it = tid; it < RB * NOUT * DK; it += T2) {
            int r  = it / (NOUT * DK);
            int ok = it % (NOUT * DK);
            int o  = ok / DK, k = ok % DK;
            const float* pp = p_s + r * RST + o * OST + k * KST;
            float s = 0.f;
            if (iter == 0) {
                #pragma unroll
                for (int n = 0; n < NN; n++) s += pp[n];
                s *= 0.1f;
            } else {
                const float* prp = pr_s + (r * NOUT + o) * NN;
                #pragma unroll
                for (int n = 0; n < NN; n++) s += prp[n] * pp[n];
            }
            v_s[it] = s;
        }
        __syncthreads();

        if (tid < RB * NOUT) {
            const float* vp = v_s + tid * DK;
            float sq = 0.f;
            #pragma unroll
            for (int k = 0; k < DK; k++) sq += vp[k] * vp[k];
            sc_s[tid] = (sq / (1.f + sq)) / sqrtf(sq);
        }
        __syncthreads();

        for (int it = tid; it < RB * NOUT * DK; it += T2)
            v_s[it] *= sc_s[it / DK];
        __syncthreads();

        if (iter < 2) {
            for (int it = tid; it < RB * NOUT * NN; it += T2) {
                int r  = it / (NOUT * NN);
                int on = it % (NOUT * NN);
                int o  = on / NN, n = on % NN;
                const float* pp = p_s + r * RST + o * OST + n;
                const float* vp = v_s + (r * NOUT + o) * DK;
                float s = 0.f;
                #pragma unroll
                for (int k = 0; k < DK; k++) s += pp[k * KST] * vp[k];
                l_s[it] = (iter == 0) ? s : (l_s[it] + s);
            }
            __syncthreads();
        }
    }

    for (int it = tid; it < RB * NOUT * DK; it += T2) {
        int r = it / (NOUT * DK);
        out[(size_t)(r0 + r) * (NOUT * DK) + (it % (NOUT * DK))] = v_s[it];
    }
}

// ---------------------------------------------------------------------------
extern "C" void kernel_launch(void* const* d_in, const int* in_sizes, int n_in,
                              void* d_out, int out_size)
{
    const float* x     = (const float*)d_in[0];
    const float* W1    = (const float*)d_in[1];
    const float* b1    = (const float*)d_in[2];
    const float* W2    = (const float*)d_in[3];
    const float* b2    = (const float*)d_in[4];
    const float* route = (const float*)d_in[5];
    float* out = (float*)d_out;

    // pack inputs into HMMA fragment layout (bf16 hi/lo)
    k0_pack_x<<<(NBAND * KS49 * 32 + 255) / 256, 256>>>(x);
    k0_pack_w<<<(NGRP * KS49 * NT * 32 + 255) / 256, 256>>>(W1);

    // tensor-core GEMM1 + fused epilogue
    const int smem1 = (128 * HSTR + GNETS * 400 + 2 * GNETS * ND) * (int)sizeof(float);
    cudaFuncSetAttribute(k1_mma, cudaFuncAttributeMaxDynamicSharedMemorySize, smem1);
    dim3 g1(B_TOTAL / 128, NGRP);
    k1_mma<<<g1, 256, smem1>>>(b1, W2, b2);

    // routing
    const int smem2 = (7200 + RB * RST + 2 * RB * NOUT * NN + RB * NOUT * DK
                       + RB * NOUT) * (int)sizeof(float);
    cudaFuncSetAttribute(k2_route, cudaFuncAttributeMaxDynamicSharedMemorySize, smem2);
    k2_route<<<B_TOTAL / RB, T2, smem2>>>(route, out);
}

// round 8
// speedup vs baseline: 2.2883x; 1.4424x over previous
#include <cuda_runtime.h>
#include <cuda_bf16.h>
#include <math.h>
#include <stdint.h>

typedef unsigned long long u64;

#define B_TOTAL 8192
#define INDIM   784
#define NN      30
#define ND      20
#define NOUT    10
#define DK      16

// ---- k1 HMMA tiling ----
#define GNETS   6                 // nets per group
#define NGRP    5                 // groups
#define NT      15                // n8 tiles per group (120 cols = 6 nets x 20, no pad)
#define NCOLS   (GNETS * ND)      // 120
#define KS49    49                // 784 / 16
#define NBAND   (B_TOTAL / 16)    // 512 m16 bands
#define HSTR    121               // epilogue smem row stride (mod 32 = 25)

// ---- k2 tiling (unchanged) ----
#define RB    8
#define T2    640
#define UPAD  12
#define KST   34
#define OST   (DK * KST + 2)
#define RST   (NOUT * OST)

// ---- device scratch ----
__device__ float g_u[(size_t)B_TOTAL * NN * ND];
__device__ uint4 g_xhf[(size_t)NBAND * KS49 * 32];       // A frags hi (12.8MB)
__device__ uint4 g_xlf[(size_t)NBAND * KS49 * 32];       // A frags lo
__device__ uint2 g_wbhf[(size_t)NGRP * KS49 * NT * 32];  // B frags hi
__device__ uint2 g_wblf[(size_t)NGRP * KS49 * NT * 32];  // B frags lo

// ---------------------------------------------------------------------------
// helpers
// ---------------------------------------------------------------------------
__device__ __forceinline__ uint32_t pbf2(float a, float b) {
    __nv_bfloat162 t = __floats2bfloat162_rn(a, b);   // a -> low half
    return *(uint32_t*)&t;
}
__device__ __forceinline__ void split2(float v, float& h, float& l) {
    __nv_bfloat16 hb = __float2bfloat16(v);
    h = __bfloat162float(hb);
    l = v - h;
}
#define MMA_BF16(d, a, b) \
    asm volatile("mma.sync.aligned.m16n8k16.row.col.f32.bf16.bf16.f32 " \
        "{%0,%1,%2,%3}, {%4,%5,%6,%7}, {%8,%9}, {%0,%1,%2,%3};" \
        : "+f"((d)[0]), "+f"((d)[1]), "+f"((d)[2]), "+f"((d)[3]) \
        : "r"((a).x), "r"((a).y), "r"((a).z), "r"((a).w), \
          "r"((b).x), "r"((b).y))

// ---------------------------------------------------------------------------
// k0x: pack x into m16n8k16 A-fragment layout, split bf16 hi/lo
// ---------------------------------------------------------------------------
__global__ __launch_bounds__(256) void k0_pack_x(const float* __restrict__ x) {
    int gid = blockIdx.x * 256 + threadIdx.x;
    if (gid >= NBAND * KS49 * 32) return;
    int lane = gid & 31;
    int t    = gid >> 5;
    int ks   = t % KS49;
    int band = t / KS49;

    int r0 = band * 16 + (lane >> 2);
    int c0 = ks * 16 + (lane & 3) * 2;
    const float* p0 = x + (size_t)r0 * INDIM + c0;
    const float* p1 = p0 + 8 * INDIM;

    float v[8] = { p0[0], p0[1], p1[0], p1[1], p0[8], p0[9], p1[8], p1[9] };
    float h[8], l[8];
    #pragma unroll
    for (int i = 0; i < 8; i++) split2(v[i], h[i], l[i]);

    g_xhf[gid] = make_uint4(pbf2(h[0], h[1]), pbf2(h[2], h[3]),
                            pbf2(h[4], h[5]), pbf2(h[6], h[7]));
    g_xlf[gid] = make_uint4(pbf2(l[0], l[1]), pbf2(l[2], l[3]),
                            pbf2(l[4], l[5]), pbf2(l[6], l[7]));
}

// ---------------------------------------------------------------------------
// k0w: pack W1 into n8k16 B-fragment layout (col-major), hi/lo
// column j of group = net (j/20), W1-col (j%20); no padding (120 = 15*8)
// ---------------------------------------------------------------------------
__global__ __launch_bounds__(256) void k0_pack_w(const float* __restrict__ W1) {
    int gid = blockIdx.x * 256 + threadIdx.x;
    if (gid >= NGRP * KS49 * NT * 32) return;
    int lane = gid & 31;
    int t    = (gid >> 5) % NT;
    int ks   = ((gid >> 5) / NT) % KS49;
    int grp  = (gid >> 5) / (NT * KS49);

    int col = t * 8 + (lane >> 2);          // 0..119
    int net = grp * GNETS + col / ND;
    int c   = col % ND;
    int k0  = ks * 16 + (lane & 3) * 2;

    const float* wp = W1 + ((size_t)net * INDIM + k0) * ND + c;
    float v[4] = { wp[0], wp[ND], wp[8 * ND], wp[9 * ND] };
    float h[4], l[4];
    #pragma unroll
    for (int i = 0; i < 4; i++) split2(v[i], h[i], l[i]);

    g_wbhf[gid] = make_uint2(pbf2(h[0], h[1]), pbf2(h[2], h[3]));
    g_wblf[gid] = make_uint2(pbf2(l[0], l[1]), pbf2(l[2], l[3]));
}

// ---------------------------------------------------------------------------
// k1: HMMA split-bf16 GEMM1 + fused GEMM2/squash epilogue
// grid = (64, 5), block = 256 (8 warps x m16). N = 120 (6 nets x 20).
// ---------------------------------------------------------------------------
__global__ __launch_bounds__(256, 2) void k1_mma(
    const float* __restrict__ b1,   // [30, 20]
    const float* __restrict__ W2,   // [30, 20, 20]
    const float* __restrict__ b2)   // [30, 20]
{
    extern __shared__ __align__(16) float sm[];
    float* hs  = sm;                        // [128][HSTR]
    float* ws2 = sm + 128 * HSTR;           // [6][400]
    float* b1s = ws2 + GNETS * 400;         // [6][20]
    float* b2s = b1s + GNETS * ND;          // [6][20]

    const int tid  = threadIdx.x;
    const int w    = tid >> 5;
    const int lane = tid & 31;
    const int grp  = blockIdx.y;
    const int row0 = blockIdx.x * 128;

    // stage epilogue weights
    for (int it = tid; it < GNETS * 400; it += 256)
        ws2[it] = W2[(size_t)(grp * GNETS) * 400 + it];
    if (tid < GNETS * ND) {
        b1s[tid] = b1[grp * GNETS * ND + tid];
        b2s[tid] = b2[grp * GNETS * ND + tid];
    }

    float acc[NT][4];
    #pragma unroll
    for (int t = 0; t < NT; t++)
        #pragma unroll
        for (int i = 0; i < 4; i++) acc[t][i] = 0.f;

    const int band = blockIdx.x * 8 + w;
    const uint4* pah = g_xhf + (size_t)band * KS49 * 32 + lane;
    const uint4* pal = g_xlf + (size_t)band * KS49 * 32 + lane;
    const uint2* pbh = g_wbhf + (size_t)grp * KS49 * NT * 32 + lane;
    const uint2* pbl = g_wblf + (size_t)grp * KS49 * NT * 32 + lane;

    uint4 ah = pah[0];
    uint4 al = pal[0];
    for (int ks = 0; ks < KS49; ks++) {
        uint4 ah_n, al_n;
        if (ks + 1 < KS49) {                 // prefetch next A fragment
            ah_n = pah[(ks + 1) * 32];
            al_n = pal[(ks + 1) * 32];
        }
        const uint2* bh = pbh + ks * NT * 32;
        const uint2* bl = pbl + ks * NT * 32;
        #pragma unroll
        for (int t = 0; t < NT; t++) {
            uint2 vh = bh[t * 32];
            uint2 vl = bl[t * 32];
            MMA_BF16(acc[t], ah, vh);   // xh * wh
            MMA_BF16(acc[t], al, vh);   // xl * wh
            MMA_BF16(acc[t], ah, vl);   // xh * wl
        }
        ah = ah_n; al = al_n;
    }

    // accumulators -> smem
    {
        const int rlo = w * 16 + (lane >> 2);
        const int cb  = (lane & 3) * 2;
        #pragma unroll
        for (int t = 0; t < NT; t++) {
            int col = t * 8 + cb;
            hs[rlo * HSTR + col]           = acc[t][0];
            hs[rlo * HSTR + col + 1]       = acc[t][1];
            hs[(rlo + 8) * HSTR + col]     = acc[t][2];
            hs[(rlo + 8) * HSTR + col + 1] = acc[t][3];
        }
    }
    __syncthreads();

    // epilogue: bias+relu, GEMM2+relu, squash -> g_u (exact fp32)
    for (int task = tid; task < 128 * GNETS; task += 256) {
        const int row = task / GNETS;
        const int g   = task % GNETS;
        const int net = grp * GNETS + g;
        float h[ND];
        #pragma unroll
        for (int c = 0; c < ND; c++) {
            float v = hs[row * HSTR + g * ND + c] + b1s[g * ND + c];
            h[c] = v > 0.f ? v : 0.f;
        }
        float h2[ND];
        float sq = 0.f;
        #pragma unroll
        for (int e = 0; e < ND; e++) {
            float s = b2s[g * ND + e];
            #pragma unroll
            for (int d = 0; d < ND; d++) s += h[d] * ws2[g * 400 + d * ND + e];
            s = s > 0.f ? s : 0.f;
            h2[e] = s;
            sq += s * s;
        }
        float scale = (sq / (1.f + sq)) / sqrtf(sq);
        float* up = g_u + (size_t)(row0 + row) * (NN * ND) + net * ND;
        #pragma unroll
        for (int e4 = 0; e4 < 5; e4++)
            *(float4*)(up + e4 * 4) = make_float4(scale * h2[e4*4],   scale * h2[e4*4+1],
                                                  scale * h2[e4*4+2], scale * h2[e4*4+3]);
    }
}

// ---------------------------------------------------------------------------
// K2: priors (packed f32x2) + dynamic routing (unchanged best version)
// ---------------------------------------------------------------------------
__device__ __forceinline__ u64 pack2(float lo, float hi) {
    u64 r; asm("mov.b64 %0, {%1,%2};" : "=l"(r) : "f"(lo), "f"(hi)); return r;
}
__device__ __forceinline__ void unpack2(u64 v, float& lo, float& hi) {
    asm("mov.b64 {%0,%1}, %2;" : "=f"(lo), "=f"(hi) : "l"(v));
}
__device__ __forceinline__ void fma2(u64& d, u64 a, u64 b) {
    asm("fma.rn.f32x2 %0, %1, %2, %0;" : "+l"(d) : "l"(a), "l"(b));
}

__global__ __launch_bounds__(T2, 1) void k2_route(
    const float* __restrict__ route,  // [10, 30, 20, 16]
    float* __restrict__ out)          // [B, 10, 16]
{
    extern __shared__ __align__(16) float sm[];
    float* u_s  = sm;                       // [600][UPAD]
    float* p_s  = sm + 7200;                // [8][RST]
    float* l_s  = p_s + RB * RST;
    float* pr_s = l_s + RB * NOUT * NN;
    float* v_s  = pr_s + RB * NOUT * NN;
    float* sc_s = v_s + RB * NOUT * DK;

    const int tid = threadIdx.x;
    const int r0  = blockIdx.x * RB;

    for (int it = tid; it < RB * NN * ND; it += T2) {
        int r = it / (NN * ND);
        int c = it % (NN * ND);
        u_s[c * UPAD + r] = g_u[(size_t)(r0 + r) * (NN * ND) + c];
    }
    __syncthreads();

    if (tid < 600) {
        const int n  = tid / 20;
        const int oo = tid % 20;
        const int o  = oo >> 1;
        const int kg = oo & 1;

        u64 acc[4][8];
        #pragma unroll
        for (int i = 0; i < 4; i++)
            #pragma unroll
            for (int j = 0; j < 8; j++) acc[i][j] = 0ull;

        const float* rp = route + (size_t)((o * NN + n) * ND) * DK + kg * 8;
        const float* up = u_s + (n * ND) * UPAD;

        #pragma unroll 4
        for (int d = 0; d < ND; d++) {
            ulonglong2 ua = *(const ulonglong2*)(up + d * UPAD);
            ulonglong2 ub = *(const ulonglong2*)(up + d * UPAD + 4);
            u64 uv[4] = {ua.x, ua.y, ub.x, ub.y};
            float4 ra = *(const float4*)(rp + (size_t)d * DK);
            float4 rb = *(const float4*)(rp + (size_t)d * DK + 4);
            u64 wv[8] = {pack2(ra.x, ra.x), pack2(ra.y, ra.y),
                         pack2(ra.z, ra.z), pack2(ra.w, ra.w),
                         pack2(rb.x, rb.x), pack2(rb.y, rb.y),
                         pack2(rb.z, rb.z), pack2(rb.w, rb.w)};
            #pragma unroll
            for (int i = 0; i < 4; i++)
                #pragma unroll
                for (int j = 0; j < 8; j++)
                    fma2(acc[i][j], uv[i], wv[j]);
        }

        #pragma unroll
        for (int i = 0; i < 4; i++)
            #pragma unroll
            for (int j = 0; j < 8; j++) {
                float lo, hi; unpack2(acc[i][j], lo, hi);
                p_s[(2 * i    ) * RST + o * OST + (kg * 8 + j) * KST + n] = lo;
                p_s[(2 * i + 1) * RST + o * OST + (kg * 8 + j) * KST + n] = hi;
            }
    }
    __syncthreads();

    for (int iter = 0; iter < 3; iter++) {
        if (iter > 0) {
            if (tid < RB * NN) {
                int r = tid / NN, n = tid % NN;
                float l[NOUT];
                float mx = -1e30f;
                #pragma unroll
                for (int o = 0; o < NOUT; o++) {
                    l[o] = l_s[(r * NOUT + o) * NN + n];
                    mx = fmaxf(mx, l[o]);
                }
                float ssum = 0.f;
                #pragma unroll
                for (int o = 0; o < NOUT; o++) { l[o] = expf(l[o] - mx); ssum += l[o]; }
                float inv = 1.f / ssum;
                #pragma unroll
                for (int o = 0; o < NOUT; o++)
                    pr_s[(r * NOUT + o) * NN + n] = l[o] * inv;
            }
            __syncthreads();
        }

        for (int it = tid; it < RB * NOUT * DK; it += T2) {
            int r  = it / (NOUT * DK);
            int ok = it % (NOUT * DK);
            int o  = ok / DK, k = ok % DK;
            const float* pp = p_s + r * RST + o * OST + k * KST;
            float s = 0.f;
            if (iter == 0) {
                #pragma unroll
                for (int n = 0; n < NN; n++) s += pp[n];
                s *= 0.1f;
            } else {
                const float* prp = pr_s + (r * NOUT + o) * NN;
                #pragma unroll
                for (int n = 0; n < NN; n++) s += prp[n] * pp[n];
            }
            v_s[it] = s;
        }
        __syncthreads();

        if (tid < RB * NOUT) {
            const float* vp = v_s + tid * DK;
            float sq = 0.f;
            #pragma unroll
            for (int k = 0; k < DK; k++) sq += vp[k] * vp[k];
            sc_s[tid] = (sq / (1.f + sq)) / sqrtf(sq);
        }
        __syncthreads();

        for (int it = tid; it < RB * NOUT * DK; it += T2)
            v_s[it] *= sc_s[it / DK];
        __syncthreads();

        if (iter < 2) {
            for (int it = tid; it < RB * NOUT * NN; it += T2) {
                int r  = it / (NOUT * NN);
                int on = it % (NOUT * NN);
                int o  = on / NN, n = on % NN;
                const float* pp = p_s + r * RST + o * OST + n;
                const float* vp = v_s + (r * NOUT + o) * DK;
                float s = 0.f;
                #pragma unroll
                for (int k = 0; k < DK; k++) s += pp[k * KST] * vp[k];
                l_s[it] = (iter == 0) ? s : (l_s[it] + s);
            }
            __syncthreads();
        }
    }

    for (int it = tid; it < RB * NOUT * DK; it += T2) {
        int r = it / (NOUT * DK);
        out[(size_t)(r0 + r) * (NOUT * DK) + (it % (NOUT * DK))] = v_s[it];
    }
}

// ---------------------------------------------------------------------------
extern "C" void kernel_launch(void* const* d_in, const int* in_sizes, int n_in,
                              void* d_out, int out_size)
{
    const float* x     = (const float*)d_in[0];
    const float* W1    = (const float*)d_in[1];
    const float* b1    = (const float*)d_in[2];
    const float* W2    = (const float*)d_in[3];
    const float* b2    = (const float*)d_in[4];
    const float* route = (const float*)d_in[5];
    float* out = (float*)d_out;

    // pack inputs into HMMA fragment layout (bf16 hi/lo)
    k0_pack_x<<<(NBAND * KS49 * 32 + 255) / 256, 256>>>(x);
    k0_pack_w<<<(NGRP * KS49 * NT * 32 + 255) / 256, 256>>>(W1);

    // tensor-core GEMM1 + fused epilogue
    const int smem1 = (128 * HSTR + GNETS * 400 + 2 * GNETS * ND) * (int)sizeof(float);
    cudaFuncSetAttribute(k1_mma, cudaFuncAttributeMaxDynamicSharedMemorySize, smem1);
    dim3 g1(B_TOTAL / 128, NGRP);
    k1_mma<<<g1, 256, smem1>>>(b1, W2, b2);

    // routing
    const int smem2 = (7200 + RB * RST + 2 * RB * NOUT * NN + RB * NOUT * DK
                       + RB * NOUT) * (int)sizeof(float);
    cudaFuncSetAttribute(k2_route, cudaFuncAttributeMaxDynamicSharedMemorySize, smem2);
    k2_route<<<B_TOTAL / RB, T2, smem2>>>(route, out);
}